// round 17
// baseline (speedup 1.0000x reference)
#include <cuda_runtime.h>

// GCN_12867722019091 — 2-layer GCN, N=50000, E=800000, HID=64, OUT=2.
// R7/R15 split-PDL chain at its edge-pass floor (~4 cyc/edge/SM). R16:
// recover boundary overhead — k_final made pure; scratch resets distributed
// to overlap-safe prologues; k_count's wait dropped (no remaining dep on
// k_final once resets moved).
//
// Reset placement safety (PDL overlaps only the immediate predecessor):
//   g_s1  reset in k_count prologue  — overlaps k_final(N-1): final doesn't touch s1.
//   g_acc reset in k_node1 prologue  — overlaps k_count: count doesn't touch acc.
//   g_deg reset in k_node2 prologue  — node2 launches after scat1.wait (= node1
//                                      complete, deg no longer needed this replay);
//                                      overlaps scat1 which doesn't touch deg.

constexpr int NN  = 50000;
constexpr int NE  = 800000;
constexpr int HID = 64;

__device__ int    g_deg[NN];
__device__ float  g_dinv[NN];
__device__ float  g_p[NN];      // x[n] * dinv[n]
__device__ float  g_s1[NN];     // layer-1 scalar scatter accumulator
__device__ float2 g_p2[NN];     // g[n,:] * dinv[n]
__device__ float2 g_acc[NN];    // layer-2 float2 scatter accumulator

__device__ __forceinline__ void pdl_wait() {
#if __CUDA_ARCH__ >= 900
    asm volatile("griddepcontrol.wait;" ::: "memory");
#endif
}
__device__ __forceinline__ void pdl_trigger() {
#if __CUDA_ARCH__ >= 900
    asm volatile("griddepcontrol.launch_dependents;" ::: "memory");
#endif
}

// ---- edge pass 1: in-degree count, 4 edges/thread; NO wait (deps all met) ----
__global__ void __launch_bounds__(256) k_count(const int* __restrict__ col) {
    int i = blockIdx.x * blockDim.x + threadIdx.x;      // NE/4 threads
    pdl_trigger();                                       // let node1 launch
    // distributed reset: s1 (overlaps final(N-1) only; final doesn't touch s1)
    if (i < NN) g_s1[i] = 0.f;
    if (i * 4 < NE) {
        int4 c = *reinterpret_cast<const int4*>(col + i * 4);
        atomicAdd(&g_deg[c.x], 1);
        atomicAdd(&g_deg[c.y], 1);
        atomicAdd(&g_deg[c.z], 1);
        atomicAdd(&g_deg[c.w], 1);
    }
}

// ---- node pass 1: dinv = rsqrt(deg+1); p = x*dinv ----
__global__ void __launch_bounds__(256) k_node1(const float* __restrict__ x) {
    int i = blockIdx.x * blockDim.x + threadIdx.x;
    float xv = (i < NN) ? x[i] : 0.f;             // prologue
    // distributed reset: acc (overlaps k_count only; count doesn't touch acc)
    if (i < NN) g_acc[i] = make_float2(0.f, 0.f);
    pdl_wait();                                   // g_deg ready
    pdl_trigger();
    if (i >= NN) return;
    float dinv = rsqrtf((float)(g_deg[i] + 1));
    g_dinv[i] = dinv;
    g_p[i]    = xv * dinv;
}

// ---- edge pass 2: s1[c] += p[r], 2 edges/thread ----
__global__ void __launch_bounds__(256) k_scat1(const int* __restrict__ row,
                                               const int* __restrict__ col) {
    int i = blockIdx.x * blockDim.x + threadIdx.x;      // NE/2 threads
    int2 r = make_int2(0, 0), c = make_int2(0, 0);
    bool ok = (i * 2 < NE);
    if (ok) {                                     // prologue: coalesced int2
        r = *reinterpret_cast<const int2*>(row + i * 2);
        c = *reinterpret_cast<const int2*>(col + i * 2);
    }
    pdl_wait();                                   // g_p ready (node1 complete)
    pdl_trigger();
    if (ok) {
        float vx = __ldg(&g_p[r.x]);              // 2 independent chains
        float vy = __ldg(&g_p[r.y]);
        atomicAdd(&g_s1[c.x], vx);
        atomicAdd(&g_s1[c.y], vy);
    }
}

// ---- node pass 2: s1 = dinv*(acc+p); h1 = relu(W1*s1+b1); p2 = (h1@W2)*dinv ----
__global__ void __launch_bounds__(256) k_node2(const float* __restrict__ W1,
                                               const float* __restrict__ b1,
                                               const float* __restrict__ W2) {
    __shared__ float sW1[HID], sb1[HID], sW2[HID * 2];
    int t = threadIdx.x;
    if (t < HID)     { sW1[t] = W1[t]; sb1[t] = b1[t]; }   // prologue
    if (t < HID * 2) { sW2[t] = W2[t]; }
    int i = blockIdx.x * blockDim.x + t;
    // distributed reset: deg (node1 finished with deg before node2 can launch;
    // overlaps scat1 only, which doesn't touch deg)
    if (i < NN) g_deg[i] = 0;
    __syncthreads();
    pdl_wait();                                   // g_s1 ready
    pdl_trigger();

    if (i >= NN) return;
    float dinv = g_dinv[i];
    float s1   = dinv * (g_s1[i] + g_p[i]);
    float a = 0.f, b = 0.f;
#pragma unroll
    for (int j = 0; j < HID; ++j) {
        float h = fmaxf(fmaf(sW1[j], s1, sb1[j]), 0.f);
        a = fmaf(h, sW2[2 * j],     a);
        b = fmaf(h, sW2[2 * j + 1], b);
    }
    g_p2[i] = make_float2(a * dinv, b * dinv);
}

// ---- edge pass 3: acc[c] += p2[r], 2 edges/thread ----
__global__ void __launch_bounds__(256) k_scat2(const int* __restrict__ row,
                                               const int* __restrict__ col) {
    int i = blockIdx.x * blockDim.x + threadIdx.x;      // NE/2 threads
    int2 r = make_int2(0, 0), c = make_int2(0, 0);
    bool ok = (i * 2 < NE);
    if (ok) {                                     // prologue
        r = *reinterpret_cast<const int2*>(row + i * 2);
        c = *reinterpret_cast<const int2*>(col + i * 2);
    }
    pdl_wait();                                   // g_p2 ready
    pdl_trigger();
    if (ok) {
        float2 vx = __ldg(&g_p2[r.x]);
        float2 vy = __ldg(&g_p2[r.y]);
        atomicAdd(&g_acc[c.x], vx);
        atomicAdd(&g_acc[c.y], vy);
    }
}

// ---- final: out = dinv*(acc+p2) + b2  (pure — no resets) ----
__global__ void __launch_bounds__(256) k_final(float* __restrict__ out,
                                               const float* __restrict__ b2) {
    int i = blockIdx.x * blockDim.x + threadIdx.x;
    float b2x = b2[0], b2y = b2[1];               // prologue
    pdl_wait();                                   // g_acc ready
    pdl_trigger();
    if (i >= NN) return;
    float dinv = g_dinv[i];
    float2 acc = g_acc[i];
    float2 p2  = g_p2[i];
    float2 o;
    o.x = fmaf(dinv, acc.x + p2.x, b2x);
    o.y = fmaf(dinv, acc.y + p2.y, b2y);
    reinterpret_cast<float2*>(out)[i] = o;
}

// ---- host ----

static void launch_pdl(const void* fn, int grid, int block, void** args) {
    cudaLaunchConfig_t cfg = {};
    cfg.gridDim  = dim3(grid, 1, 1);
    cfg.blockDim = dim3(block, 1, 1);
    cfg.stream   = 0;
    cudaLaunchAttribute attr[1];
    attr[0].id = cudaLaunchAttributeProgrammaticStreamSerialization;
    attr[0].val.programmaticStreamSerializationAllowed = 1;
    cfg.attrs    = attr;
    cfg.numAttrs = 1;
    cudaLaunchKernelExC(&cfg, fn, args);
}

extern "C" void kernel_launch(void* const* d_in, const int* in_sizes, int n_in,
                              void* d_out, int out_size) {
    const float* x   = (const float*)d_in[0];
    const int*   ei  = (const int*)d_in[1];   // [2, NE]
    const float* W1  = (const float*)d_in[2];
    const float* b1  = (const float*)d_in[3];
    const float* W2  = (const float*)d_in[4];
    const float* b2  = (const float*)d_in[5];
    float* out = (float*)d_out;

    const int* row = ei;
    const int* col = ei + NE;

    const int TB = 256;
    const int nodeBlocks  = (NN + TB - 1) / TB;
    const int edge4Blocks = (NE / 4 + TB - 1) / TB;   // count: 4 edges/thread
    const int edge2Blocks = (NE / 2 + TB - 1) / TB;   // scats: 2 edges/thread

    { void* a[] = { (void*)&col };                        launch_pdl((const void*)k_count, edge4Blocks, TB, a); }
    { void* a[] = { (void*)&x };                          launch_pdl((const void*)k_node1, nodeBlocks, TB, a); }
    { void* a[] = { (void*)&row, (void*)&col };           launch_pdl((const void*)k_scat1, edge2Blocks, TB, a); }
    { void* a[] = { (void*)&W1, (void*)&b1, (void*)&W2 }; launch_pdl((const void*)k_node2, nodeBlocks, TB, a); }
    { void* a[] = { (void*)&row, (void*)&col };           launch_pdl((const void*)k_scat2, edge2Blocks, TB, a); }
    { void* a[] = { (void*)&out, (void*)&b2 };            launch_pdl((const void*)k_final, nodeBlocks, TB, a); }
}